// round 12
// baseline (speedup 1.0000x reference)
#include <cuda_runtime.h>
#include <cuda_fp16.h>
#include <cstdint>

// C = triu(A @ B), A,B upper-triangular fp32, N=4096.
// Round 12: saturated legacy-HMMA model (rt~17.5cyc) => minimize HMMA count.
//   - 128x128 tiles (was 128x256): -4.3% padded FLOPs, finer LPT packing.
//   - SPLIT_L=5 on the 128-grid: smaller max piece -> tighter tail.
//   - fp16 m16n8k16 + ldmatrix, 4-stage cp.async, fused prep (A cvt, B^T cvt,
//     selective C zeroing), in-kernel schedule decode, split-K atomics.

#define N_DIM 4096
#define BM 128
#define BN 128
#define BK 64
#define STAGES 4
#define NTHREADS 256
#define SPLIT_L 5     // max 128-K-chunks per piece

#define APh 72
#define BPh 72
#define A_STAGE_H (BM * APh)                       // 9216
#define B_STAGE_H (BN * BPh)                       // 9216
#define B_BASE_H  (STAGES * A_STAGE_H)             // 36864
#define SMEM_H    (B_BASE_H + STAGES * B_STAGE_H)  // 73728 halfs = 147456 B

__device__ __half g_Ah[(size_t)N_DIM * N_DIM];   // A half [m][k]; zero-init
__device__ __half g_Bt[(size_t)N_DIM * N_DIM];   // B^T half [n][k]; zero-init

__device__ __forceinline__ uint32_t smem_u32(const void* p) {
    uint32_t a;
    asm("{ .reg .u64 t; cvta.to.shared.u64 t, %1; cvt.u32.u64 %0, t; }" : "=r"(a) : "l"(p));
    return a;
}
__device__ __forceinline__ void cp_async16(uint32_t dst, const void* src) {
    asm volatile("cp.async.cg.shared.global [%0], [%1], 16;" :: "r"(dst), "l"(src));
}
__device__ __forceinline__ void red_add_f32(float* p, float v) {
    asm volatile("red.global.add.f32 [%0], %1;" :: "l"(p), "f"(v) : "memory");
}
#define LDSM_X4(r0, r1, r2, r3, a)                                              \
    asm volatile("ldmatrix.sync.aligned.m8n8.x4.shared.b16 {%0,%1,%2,%3}, [%4];" \
                 : "=r"(r0), "=r"(r1), "=r"(r2), "=r"(r3) : "r"(a))

// ---------------- Fused pre-pass + selective C zeroing ----------------
// blocks [0, 4096): convert A row (k >= row).
// blocks [4096, +16384): B^T 32x32 tile (skip k_blk > n_blk).
// blocks [4096+16384, +2048): zero 64-row slabs of 128x128 C tiles that are
//   lower-triangular or split-K targets.
#define PREP_A 4096
#define PREP_B (128 * 128)
#define PREP_Z (1024 * 2)

__global__ __launch_bounds__(256) void prep_kernel(const float* __restrict__ A,
                                                   const float* __restrict__ B,
                                                   float* __restrict__ C) {
    const int b = blockIdx.x;
    if (b < PREP_A) {
        const int row = b;
        const int k0 = row & ~31;
        const float* src = A + (size_t)row * N_DIM;
        __half* dst = g_Ah + (size_t)row * N_DIM;
        for (int k = k0 + threadIdx.x * 4; k < N_DIM; k += 256 * 4) {
            float4 v = *reinterpret_cast<const float4*>(src + k);
            __half2 h0 = __floats2half2_rn(v.x, v.y);
            __half2 h1 = __floats2half2_rn(v.z, v.w);
            uint2 u;
            u.x = *reinterpret_cast<uint32_t*>(&h0);
            u.y = *reinterpret_cast<uint32_t*>(&h1);
            *reinterpret_cast<uint2*>(dst + k) = u;
        }
    } else if (b < PREP_A + PREP_B) {
        const int t = b - PREP_A;
        const int bx = (t & 127) * 32;   // n block
        const int by = (t >> 7) * 32;    // k block
        if (by > bx) return;             // zero region of B
        __shared__ float tt[32][33];
        const int x = threadIdx.x & 31;
        const int y0 = threadIdx.x >> 5;
#pragma unroll
        for (int i = y0; i < 32; i += 8)
            tt[i][x] = B[(size_t)(by + i) * N_DIM + bx + x];
        __syncthreads();
#pragma unroll
        for (int i = y0; i < 32; i += 8)
            g_Bt[(size_t)(bx + i) * N_DIM + by + x] = __float2half_rn(tt[x][i]);
    } else {
        const int z = b - PREP_A - PREP_B;       // [0, 2048)
        const int t = z >> 1;                    // 128x128 tile id [0, 1024)
        const int sub = z & 1;                   // 64-row slab
        const int it = t & 31;
        const int jt = t >> 5;
        const int L = jt - it + 1;
        if (it <= jt && L <= SPLIT_L) return;    // fully written by GEMM store
        const int row = it * BM + sub * 64 + (threadIdx.x >> 2);
        float4* dst = reinterpret_cast<float4*>(
            C + (size_t)row * N_DIM + jt * BN + (threadIdx.x & 3) * 32);
        const float4 zv = make_float4(0.f, 0.f, 0.f, 0.f);
#pragma unroll
        for (int k = 0; k < 8; k++) dst[k] = zv;
    }
}

// ---------------- Main GEMM ----------------

__global__ __launch_bounds__(NTHREADS, 1)
void triu_gemm_f16mma_kernel(float* __restrict__ C)
{
    extern __shared__ __half smh[];
    const uint32_t smb = smem_u32(smh);

    const int tid  = threadIdx.x;
    const int wid  = tid >> 5;
    const int lane = tid & 31;
    const int qrow = lane >> 2;
    const int qcol = lane & 3;

    // Decode blockIdx -> (it, jt, k range) over 128x128 upper tiles.
    // L = jt-it+1 in 128-chunks, enumerated L=32..1; L > SPLIT_L splits
    // into ceil(L/SPLIT_L) even pieces.
    int it, jt, k_beg, k_end, L;
    {
        int r = blockIdx.x;
        L = 32;
        int p;
        for (;; L--) {
            const int njt = 33 - L;
            p = (L + SPLIT_L - 1) / SPLIT_L;
            if (r < njt * p) break;
            r -= njt * p;
        }
        jt = (L - 1) + r / p;
        const int q = r % p;
        it = jt - L + 1;
        k_beg = (it + (q * L) / p) * 128;
        k_end = (it + ((q + 1) * L) / p) * 128;
    }
    const int nch = (k_end - k_beg) / BK;
    const int split = (L > SPLIT_L);

    const int row0 = it * BM;
    const int col0 = jt * BN;

    // Warps 2(m) x 4(n): warp tile 64 x 32.
    const int wm = (wid & 1) * 64;
    const int wn = (wid >> 1) * 32;

    float acc[4][4][4];
#pragma unroll
    for (int i = 0; i < 4; i++)
#pragma unroll
        for (int j = 0; j < 4; j++)
#pragma unroll
            for (int r2 = 0; r2 < 4; r2++) acc[i][j][r2] = 0.0f;

    const int arow = tid >> 3;
    const int aseg = tid & 7;

    const __half* Ag = g_Ah + (size_t)(row0 + arow) * N_DIM + aseg * 8;
    const __half* Bg = g_Bt + (size_t)(col0 + arow) * N_DIM + aseg * 8;

#define LOAD_STAGE(s, kc)                                                        \
    do {                                                                         \
        const uint32_t abase = smb + ((s) * A_STAGE_H) * 2;                      \
        const uint32_t bbase = smb + (B_BASE_H + (s) * B_STAGE_H) * 2;           \
        _Pragma("unroll")                                                        \
        for (int r1 = 0; r1 < 4; r1++)                                          \
            cp_async16(abase + ((arow + r1 * 32) * APh + aseg * 8) * 2,          \
                       Ag + (size_t)(r1 * 32) * N_DIM + (kc));                   \
        _Pragma("unroll")                                                        \
        for (int r1 = 0; r1 < 4; r1++)                                          \
            cp_async16(bbase + ((arow + r1 * 32) * BPh + aseg * 8) * 2,          \
                       Bg + (size_t)(r1 * 32) * N_DIM + (kc));                   \
    } while (0)

    const uint32_t a_lane =
        ((wm + ((lane >> 3) & 1) * 8 + (lane & 7)) * APh + (lane >> 4) * 8) * 2;
    const uint32_t b_lane =
        ((wn + (lane >> 4) * 8 + (lane & 7)) * BPh + ((lane >> 3) & 1) * 8) * 2;

    // Prologue (guarded: short pieces can have nch < STAGES-1).
#pragma unroll
    for (int s = 0; s < STAGES - 1; s++) {
        if (s < nch) LOAD_STAGE(s, k_beg + s * BK);
        asm volatile("cp.async.commit_group;" ::: "memory");
    }

    for (int i = 0; i < nch; i++) {
        asm volatile("cp.async.wait_group %0;" :: "n"(STAGES - 2) : "memory");
        __syncthreads();

        if (i + STAGES - 1 < nch)
            LOAD_STAGE((i + STAGES - 1) % STAGES, k_beg + (i + STAGES - 1) * BK);
        asm volatile("cp.async.commit_group;" ::: "memory");

        const int s = i % STAGES;
        const uint32_t a_base = smb + (s * A_STAGE_H) * 2 + a_lane;
        const uint32_t b_base = smb + (B_BASE_H + s * B_STAGE_H) * 2 + b_lane;

        uint32_t af[2][4][4], bf[2][4][2];
#pragma unroll
        for (int mt = 0; mt < 4; mt++)
            LDSM_X4(af[0][mt][0], af[0][mt][1], af[0][mt][2], af[0][mt][3],
                    a_base + (mt * 16 * APh) * 2);
#pragma unroll
        for (int p = 0; p < 2; p++)
            LDSM_X4(bf[0][2 * p][0], bf[0][2 * p][1],
                    bf[0][2 * p + 1][0], bf[0][2 * p + 1][1],
                    b_base + (p * 16 * BPh) * 2);

#pragma unroll
        for (int ks = 0; ks < BK / 16; ks++) {
            const int cur = ks & 1;
            const int nxt = cur ^ 1;
            if (ks < BK / 16 - 1) {
                const uint32_t ko = ((ks + 1) * 16) * 2;
#pragma unroll
                for (int mt = 0; mt < 4; mt++)
                    LDSM_X4(af[nxt][mt][0], af[nxt][mt][1],
                            af[nxt][mt][2], af[nxt][mt][3],
                            a_base + (mt * 16 * APh) * 2 + ko);
#pragma unroll
                for (int p = 0; p < 2; p++)
                    LDSM_X4(bf[nxt][2 * p][0], bf[nxt][2 * p][1],
                            bf[nxt][2 * p + 1][0], bf[nxt][2 * p + 1][1],
                            b_base + (p * 16 * BPh) * 2 + ko);
            }
#pragma unroll
            for (int mt = 0; mt < 4; mt++)
#pragma unroll
                for (int nt = 0; nt < 4; nt++) {
                    asm volatile(
                        "mma.sync.aligned.m16n8k16.row.col.f32.f16.f16.f32 "
                        "{%0,%1,%2,%3}, {%4,%5,%6,%7}, {%8,%9}, {%0,%1,%2,%3};"
                        : "+f"(acc[mt][nt][0]), "+f"(acc[mt][nt][1]),
                          "+f"(acc[mt][nt][2]), "+f"(acc[mt][nt][3])
                        : "r"(af[cur][mt][0]), "r"(af[cur][mt][1]),
                          "r"(af[cur][mt][2]), "r"(af[cur][mt][3]),
                          "r"(bf[cur][nt][0]), "r"(bf[cur][nt][1]));
                }
        }
    }

    // ---- Epilogue ----
    if (split) {
#pragma unroll
        for (int mt = 0; mt < 4; mt++) {
            const int r_lo = row0 + wm + mt * 16 + qrow;
            float* crow_lo = C + (size_t)r_lo * N_DIM;
            float* crow_hi = crow_lo + (size_t)8 * N_DIM;
#pragma unroll
            for (int nt = 0; nt < 4; nt++) {
                const int gc = col0 + wn + nt * 8 + qcol * 2;
                red_add_f32(crow_lo + gc,     acc[mt][nt][0]);
                red_add_f32(crow_lo + gc + 1, acc[mt][nt][1]);
                red_add_f32(crow_hi + gc,     acc[mt][nt][2]);
                red_add_f32(crow_hi + gc + 1, acc[mt][nt][3]);
            }
        }
    } else {
#pragma unroll
        for (int mt = 0; mt < 4; mt++) {
            const int r_lo = row0 + wm + mt * 16 + qrow;
            const int r_hi = r_lo + 8;
            float* crow_lo = C + (size_t)r_lo * N_DIM;
            float* crow_hi = C + (size_t)r_hi * N_DIM;
#pragma unroll
            for (int nt = 0; nt < 4; nt++) {
                const int gc = col0 + wn + nt * 8 + qcol * 2;
                float2 v0, v1;
                v0.x = (gc + 0 >= r_lo) ? acc[mt][nt][0] : 0.0f;
                v0.y = (gc + 1 >= r_lo) ? acc[mt][nt][1] : 0.0f;
                v1.x = (gc + 0 >= r_hi) ? acc[mt][nt][2] : 0.0f;
                v1.y = (gc + 1 >= r_hi) ? acc[mt][nt][3] : 0.0f;
                *reinterpret_cast<float2*>(crow_lo + gc) = v0;
                *reinterpret_cast<float2*>(crow_hi + gc) = v1;
            }
        }
    }
}

extern "C" void kernel_launch(void* const* d_in, const int* in_sizes, int n_in,
                              void* d_out, int out_size) {
    const float* A = (const float*)d_in[0];
    const float* B = (const float*)d_in[1];
    float* C = (float*)d_out;

    // Grid size = number of schedule pieces (matches device decode).
    int cnt = 0;
    for (int L = 32; L >= 1; L--) {
        const int njt = 33 - L;
        const int p = (L + SPLIT_L - 1) / SPLIT_L;
        cnt += njt * p;
    }

    cudaFuncSetAttribute(triu_gemm_f16mma_kernel,
                         cudaFuncAttributeMaxDynamicSharedMemorySize, SMEM_H * 2);

    prep_kernel<<<PREP_A + PREP_B + PREP_Z, 256>>>(A, B, C);
    triu_gemm_f16mma_kernel<<<cnt, NTHREADS, SMEM_H * 2>>>(C);
}

// round 15
// speedup vs baseline: 1.2138x; 1.2138x over previous
#include <cuda_runtime.h>
#include <cuda_fp16.h>
#include <cstdint>

// C = triu(A @ B), A,B upper-triangular fp32, N=4096.
// Round 15: R14 with the REAL misalignment fixed — smem transpose staging
// pitch 65 -> 68 floats (odd rows were not 16B-aligned for float4 stores).
// GEMM = R11 config (128x256 tiles, SPLIT_L=8, legacy-HMMA wall).

#define N_DIM 4096
#define BM 128
#define BN 256
#define BK 64
#define STAGES 4
#define NTHREADS 256
#define SPLIT_L 8

#define APh 72
#define BPh 72
#define A_STAGE_H (BM * APh)                       // 9216
#define B_STAGE_H (BN * BPh)                       // 18432
#define B_BASE_H  (STAGES * A_STAGE_H)             // 36864
#define SMEM_H    (B_BASE_H + STAGES * B_STAGE_H)  // 110592 halfs = 221184 B

__device__ __half g_Ah[(size_t)N_DIM * N_DIM];   // A half [m][k]; zero-init
__device__ __half g_Bt[(size_t)N_DIM * N_DIM];   // B^T half [n][k]; zero-init

__device__ __forceinline__ uint32_t smem_u32(const void* p) {
    uint32_t a;
    asm("{ .reg .u64 t; cvta.to.shared.u64 t, %1; cvt.u32.u64 %0, t; }" : "=r"(a) : "l"(p));
    return a;
}
__device__ __forceinline__ void cp_async16(uint32_t dst, const void* src) {
    asm volatile("cp.async.cg.shared.global [%0], [%1], 16;" :: "r"(dst), "l"(src));
}
__device__ __forceinline__ void red_add_f32(float* p, float v) {
    asm volatile("red.global.add.f32 [%0], %1;" :: "l"(p), "f"(v) : "memory");
}
#define LDSM_X4(r0, r1, r2, r3, a)                                              \
    asm volatile("ldmatrix.sync.aligned.m8n8.x4.shared.b16 {%0,%1,%2,%3}, [%4];" \
                 : "=r"(r0), "=r"(r1), "=r"(r2), "=r"(r3) : "r"(a))

// ---------------- Fused pre-pass + selective C zeroing ----------------
#define PREP_A 4096
#define PREP_B (64 * 64)
#define PREP_Z (512 * 4)
#define TP 68   // smem transpose pitch (floats): multiple of 4 -> float4 aligned

__global__ __launch_bounds__(256) void prep_kernel(const float* __restrict__ A,
                                                   const float* __restrict__ B,
                                                   float* __restrict__ C) {
    const int b = blockIdx.x;
    if (b < PREP_A) {
        const int row = b;
        const int k0 = row & ~31;
        const float* src = A + (size_t)row * N_DIM;
        __half* dst = g_Ah + (size_t)row * N_DIM;
        for (int k = k0 + threadIdx.x * 4; k < N_DIM; k += 256 * 4) {
            float4 v = *reinterpret_cast<const float4*>(src + k);
            __half2 h0 = __floats2half2_rn(v.x, v.y);
            __half2 h1 = __floats2half2_rn(v.z, v.w);
            uint2 u;
            u.x = *reinterpret_cast<uint32_t*>(&h0);
            u.y = *reinterpret_cast<uint32_t*>(&h1);
            *reinterpret_cast<uint2*>(dst + k) = u;
        }
    } else if (b < PREP_A + PREP_B) {
        const int t = b - PREP_A;
        const int bx = (t & 63) * 64;    // n block
        const int by = (t >> 6) * 64;    // k block
        if (by > bx) return;             // zero region of B (k > n)
        __shared__ float tt[64 * TP];
        const int seg4 = threadIdx.x & 15;        // float4 seg within row
        const int r0   = threadIdx.x >> 4;        // 16 rows per pass
#pragma unroll
        for (int i = r0; i < 64; i += 16)
            *reinterpret_cast<float4*>(&tt[i * TP + seg4 * 4]) =
                *reinterpret_cast<const float4*>(
                    &B[(size_t)(by + i) * N_DIM + bx + seg4 * 4]);
        __syncthreads();
        // Write g_Bt rows: n = tid>>2, each thread converts 16 k-values.
        const int n  = threadIdx.x >> 2;
        const int ks = (threadIdx.x & 3) * 16;
        uint4 hbuf4[2];                       // 16B-aligned staging
        __half* hbuf = reinterpret_cast<__half*>(hbuf4);
#pragma unroll
        for (int k = 0; k < 16; k++)
            hbuf[k] = __float2half_rn(tt[(ks + k) * TP + n]);
        uint4* dst = reinterpret_cast<uint4*>(
            g_Bt + (size_t)(bx + n) * N_DIM + by + ks);
        dst[0] = hbuf4[0];
        dst[1] = hbuf4[1];
    } else {
        const int z = b - PREP_A - PREP_B;       // [0, 2048)
        const int t = z >> 2;                    // 128x256 tile id [0, 512)
        const int sub = z & 3;                   // 32-row slab
        const int it = t & 31;
        const int jt = t >> 5;
        const int L = 2 * jt + 2 - it;           // K-chunks if upper tile
        const bool upper = (it <= 2 * jt + 1);
        if (upper && L <= SPLIT_L) return;       // fully written by GEMM store
        const int row = it * BM + sub * 32 + (threadIdx.x >> 3);
        float4* dst = reinterpret_cast<float4*>(
            C + (size_t)row * N_DIM + jt * BN) + (threadIdx.x & 7);
        const float4 zv = make_float4(0.f, 0.f, 0.f, 0.f);
#pragma unroll
        for (int k = 0; k < 8; k++) dst[k * 8] = zv;
    }
}

// ---------------- Main GEMM (R11 config) ----------------

__global__ __launch_bounds__(NTHREADS, 1)
void triu_gemm_f16mma_kernel(float* __restrict__ C)
{
    extern __shared__ __half smh[];
    const uint32_t smb = smem_u32(smh);

    const int tid  = threadIdx.x;
    const int wid  = tid >> 5;
    const int lane = tid & 31;
    const int qrow = lane >> 2;
    const int qcol = lane & 3;

    int it, jt, k_beg, k_end, L;
    {
        int r = blockIdx.x;
        L = 32;
        int jt0, p, njt;
        for (;; L--) {
            jt0 = (L - 1) >> 1;
            p = (L + 7) >> 3;
            njt = 16 - jt0;
            if (r < njt * p) break;
            r -= njt * p;
        }
        jt = jt0 + r / p;
        const int q = r % p;
        it = 2 * jt + 2 - L;
        k_beg = (it + (q * L) / p) * 128;
        k_end = (it + ((q + 1) * L) / p) * 128;
    }
    const int nch = (k_end - k_beg) / BK;
    const int split = (L > SPLIT_L);

    const int row0 = it * BM;
    const int col0 = jt * BN;

    const int wm = (wid & 1) * 64;
    const int wn = (wid >> 1) * 64;

    float acc[4][8][4];
#pragma unroll
    for (int i = 0; i < 4; i++)
#pragma unroll
        for (int j = 0; j < 8; j++)
#pragma unroll
            for (int r2 = 0; r2 < 4; r2++) acc[i][j][r2] = 0.0f;

    const int arow = tid >> 3;
    const int aseg = tid & 7;

    const __half* Ag = g_Ah + (size_t)(row0 + arow) * N_DIM + aseg * 8;
    const __half* Bg = g_Bt + (size_t)(col0 + arow) * N_DIM + aseg * 8;

#define LOAD_STAGE(s, kc)                                                        \
    do {                                                                         \
        const uint32_t abase = smb + ((s) * A_STAGE_H) * 2;                      \
        const uint32_t bbase = smb + (B_BASE_H + (s) * B_STAGE_H) * 2;           \
        _Pragma("unroll")                                                        \
        for (int r1 = 0; r1 < 4; r1++)                                          \
            cp_async16(abase + ((arow + r1 * 32) * APh + aseg * 8) * 2,          \
                       Ag + (size_t)(r1 * 32) * N_DIM + (kc));                   \
        _Pragma("unroll")                                                        \
        for (int r1 = 0; r1 < 8; r1++)                                          \
            cp_async16(bbase + ((arow + r1 * 32) * BPh + aseg * 8) * 2,          \
                       Bg + (size_t)(r1 * 32) * N_DIM + (kc));                   \
    } while (0)

    const uint32_t a_lane =
        ((wm + ((lane >> 3) & 1) * 8 + (lane & 7)) * APh + (lane >> 4) * 8) * 2;
    const uint32_t b_lane =
        ((wn + (lane >> 4) * 8 + (lane & 7)) * BPh + ((lane >> 3) & 1) * 8) * 2;

#pragma unroll
    for (int s = 0; s < STAGES - 1; s++) {
        if (s < nch) LOAD_STAGE(s, k_beg + s * BK);
        asm volatile("cp.async.commit_group;" ::: "memory");
    }

    for (int i = 0; i < nch; i++) {
        asm volatile("cp.async.wait_group %0;" :: "n"(STAGES - 2) : "memory");
        __syncthreads();

        if (i + STAGES - 1 < nch)
            LOAD_STAGE((i + STAGES - 1) % STAGES, k_beg + (i + STAGES - 1) * BK);
        asm volatile("cp.async.commit_group;" ::: "memory");

        const int s = i % STAGES;
        const uint32_t a_base = smb + (s * A_STAGE_H) * 2 + a_lane;
        const uint32_t b_base = smb + (B_BASE_H + s * B_STAGE_H) * 2 + b_lane;

        uint32_t af[2][4][4], bf[2][8][2];
#pragma unroll
        for (int mt = 0; mt < 4; mt++)
            LDSM_X4(af[0][mt][0], af[0][mt][1], af[0][mt][2], af[0][mt][3],
                    a_base + (mt * 16 * APh) * 2);
#pragma unroll
        for (int p = 0; p < 4; p++)
            LDSM_X4(bf[0][2 * p][0], bf[0][2 * p][1],
                    bf[0][2 * p + 1][0], bf[0][2 * p + 1][1],
                    b_base + (p * 16 * BPh) * 2);

#pragma unroll
        for (int ks = 0; ks < BK / 16; ks++) {
            const int cur = ks & 1;
            const int nxt = cur ^ 1;
            if (ks < BK / 16 - 1) {
                const uint32_t ko = ((ks + 1) * 16) * 2;
#pragma unroll
                for (int mt = 0; mt < 4; mt++)
                    LDSM_X4(af[nxt][mt][0], af[nxt][mt][1],
                            af[nxt][mt][2], af[nxt][mt][3],
                            a_base + (mt * 16 * APh) * 2 + ko);
#pragma unroll
                for (int p = 0; p < 4; p++)
                    LDSM_X4(bf[nxt][2 * p][0], bf[nxt][2 * p][1],
                            bf[nxt][2 * p + 1][0], bf[nxt][2 * p + 1][1],
                            b_base + (p * 16 * BPh) * 2 + ko);
            }
#pragma unroll
            for (int mt = 0; mt < 4; mt++)
#pragma unroll
                for (int nt = 0; nt < 8; nt++) {
                    asm volatile(
                        "mma.sync.aligned.m16n8k16.row.col.f32.f16.f16.f32 "
                        "{%0,%1,%2,%3}, {%4,%5,%6,%7}, {%8,%9}, {%0,%1,%2,%3};"
                        : "+f"(acc[mt][nt][0]), "+f"(acc[mt][nt][1]),
                          "+f"(acc[mt][nt][2]), "+f"(acc[mt][nt][3])
                        : "r"(af[cur][mt][0]), "r"(af[cur][mt][1]),
                          "r"(af[cur][mt][2]), "r"(af[cur][mt][3]),
                          "r"(bf[cur][nt][0]), "r"(bf[cur][nt][1]));
                }
        }
    }
    __syncthreads();

    // ---- Epilogue ----
    if (split) {
#pragma unroll
        for (int mt = 0; mt < 4; mt++) {
            const int r_lo = row0 + wm + mt * 16 + qrow;
            float* crow_lo = C + (size_t)r_lo * N_DIM;
            float* crow_hi = crow_lo + (size_t)8 * N_DIM;
#pragma unroll
            for (int nt = 0; nt < 8; nt++) {
                const int gc = col0 + wn + nt * 8 + qcol * 2;
                red_add_f32(crow_lo + gc,     acc[mt][nt][0]);
                red_add_f32(crow_lo + gc + 1, acc[mt][nt][1]);
                red_add_f32(crow_hi + gc,     acc[mt][nt][2]);
                red_add_f32(crow_hi + gc + 1, acc[mt][nt][3]);
            }
        }
    } else {
#pragma unroll
        for (int mt = 0; mt < 4; mt++) {
            const int r_lo = row0 + wm + mt * 16 + qrow;
            const int r_hi = r_lo + 8;
            float* crow_lo = C + (size_t)r_lo * N_DIM;
            float* crow_hi = C + (size_t)r_hi * N_DIM;
#pragma unroll
            for (int nt = 0; nt < 8; nt++) {
                const int gc = col0 + wn + nt * 8 + qcol * 2;
                float2 v0, v1;
                v0.x = (gc + 0 >= r_lo) ? acc[mt][nt][0] : 0.0f;
                v0.y = (gc + 1 >= r_lo) ? acc[mt][nt][1] : 0.0f;
                v1.x = (gc + 0 >= r_hi) ? acc[mt][nt][2] : 0.0f;
                v1.y = (gc + 1 >= r_hi) ? acc[mt][nt][3] : 0.0f;
                *reinterpret_cast<float2*>(crow_lo + gc) = v0;
                *reinterpret_cast<float2*>(crow_hi + gc) = v1;
            }
        }
    }
}

extern "C" void kernel_launch(void* const* d_in, const int* in_sizes, int n_in,
                              void* d_out, int out_size) {
    const float* A = (const float*)d_in[0];
    const float* B = (const float*)d_in[1];
    float* C = (float*)d_out;

    int cnt = 0;
    for (int L = 32; L >= 1; L--) {
        const int jt0 = (L - 1) >> 1;
        const int p = (L + 7) >> 3;
        cnt += (16 - jt0) * p;
    }

    cudaFuncSetAttribute(triu_gemm_f16mma_kernel,
                         cudaFuncAttributeMaxDynamicSharedMemorySize, SMEM_H * 2);

    prep_kernel<<<PREP_A + PREP_B + PREP_Z, 256>>>(A, B, C);
    triu_gemm_f16mma_kernel<<<cnt, NTHREADS, SMEM_H * 2>>>(C);
}

// round 16
// speedup vs baseline: 1.2258x; 1.0099x over previous
#include <cuda_runtime.h>
#include <cuda_fp16.h>
#include <cstdint>

// C = triu(A @ B), A,B upper-triangular fp32, N=4096.
// Round 16: lower-triangle C zeroing moved INTO the GEMM prologue (fire-and-
// forget STG into the GEMM's 93%-idle DRAM window); prep zeroes only the
// split-K target tiles (atomic-ordering requirement). GEMM = R11 config.

#define N_DIM 4096
#define BM 128
#define BN 256
#define BK 64
#define STAGES 4
#define NTHREADS 256
#define SPLIT_L 8

#define APh 72
#define BPh 72
#define A_STAGE_H (BM * APh)                       // 9216
#define B_STAGE_H (BN * BPh)                       // 18432
#define B_BASE_H  (STAGES * A_STAGE_H)             // 36864
#define SMEM_H    (B_BASE_H + STAGES * B_STAGE_H)  // 110592 halfs = 221184 B

__device__ __half g_Ah[(size_t)N_DIM * N_DIM];   // A half [m][k]; zero-init
__device__ __half g_Bt[(size_t)N_DIM * N_DIM];   // B^T half [n][k]; zero-init

__device__ __forceinline__ uint32_t smem_u32(const void* p) {
    uint32_t a;
    asm("{ .reg .u64 t; cvta.to.shared.u64 t, %1; cvt.u32.u64 %0, t; }" : "=r"(a) : "l"(p));
    return a;
}
__device__ __forceinline__ void cp_async16(uint32_t dst, const void* src) {
    asm volatile("cp.async.cg.shared.global [%0], [%1], 16;" :: "r"(dst), "l"(src));
}
__device__ __forceinline__ void red_add_f32(float* p, float v) {
    asm volatile("red.global.add.f32 [%0], %1;" :: "l"(p), "f"(v) : "memory");
}
#define LDSM_X4(r0, r1, r2, r3, a)                                              \
    asm volatile("ldmatrix.sync.aligned.m8n8.x4.shared.b16 {%0,%1,%2,%3}, [%4];" \
                 : "=r"(r0), "=r"(r1), "=r"(r2), "=r"(r3) : "r"(a))

// ---------------- Fused pre-pass + split-tile C zeroing ----------------
#define PREP_A 4096
#define PREP_B (64 * 64)
#define PREP_Z (512 * 4)
#define TP 68   // smem transpose pitch (floats): multiple of 4 -> float4 aligned

__global__ __launch_bounds__(256) void prep_kernel(const float* __restrict__ A,
                                                   const float* __restrict__ B,
                                                   float* __restrict__ C) {
    const int b = blockIdx.x;
    if (b < PREP_A) {
        const int row = b;
        const int k0 = row & ~31;
        const float* src = A + (size_t)row * N_DIM;
        __half* dst = g_Ah + (size_t)row * N_DIM;
        for (int k = k0 + threadIdx.x * 4; k < N_DIM; k += 256 * 4) {
            float4 v = *reinterpret_cast<const float4*>(src + k);
            __half2 h0 = __floats2half2_rn(v.x, v.y);
            __half2 h1 = __floats2half2_rn(v.z, v.w);
            uint2 u;
            u.x = *reinterpret_cast<uint32_t*>(&h0);
            u.y = *reinterpret_cast<uint32_t*>(&h1);
            *reinterpret_cast<uint2*>(dst + k) = u;
        }
    } else if (b < PREP_A + PREP_B) {
        const int t = b - PREP_A;
        const int bx = (t & 63) * 64;    // n block
        const int by = (t >> 6) * 64;    // k block
        if (by > bx) return;             // zero region of B (k > n)
        __shared__ float tt[64 * TP];
        const int seg4 = threadIdx.x & 15;
        const int r0   = threadIdx.x >> 4;
#pragma unroll
        for (int i = r0; i < 64; i += 16)
            *reinterpret_cast<float4*>(&tt[i * TP + seg4 * 4]) =
                *reinterpret_cast<const float4*>(
                    &B[(size_t)(by + i) * N_DIM + bx + seg4 * 4]);
        __syncthreads();
        const int n  = threadIdx.x >> 2;
        const int ks = (threadIdx.x & 3) * 16;
        uint4 hbuf4[2];
        __half* hbuf = reinterpret_cast<__half*>(hbuf4);
#pragma unroll
        for (int k = 0; k < 16; k++)
            hbuf[k] = __float2half_rn(tt[(ks + k) * TP + n]);
        uint4* dst = reinterpret_cast<uint4*>(
            g_Bt + (size_t)(bx + n) * N_DIM + by + ks);
        dst[0] = hbuf4[0];
        dst[1] = hbuf4[1];
    } else {
        // Zero ONLY split-K target tiles (must precede GEMM atomics).
        const int z = b - PREP_A - PREP_B;       // [0, 2048)
        const int t = z >> 2;                    // 128x256 tile id [0, 512)
        const int sub = z & 3;                   // 32-row slab
        const int it = t & 31;
        const int jt = t >> 5;
        const int L = 2 * jt + 2 - it;
        const bool upper = (it <= 2 * jt + 1);
        if (!(upper && L > SPLIT_L)) return;     // lower tiles zeroed in GEMM
        const int row = it * BM + sub * 32 + (threadIdx.x >> 3);
        float4* dst = reinterpret_cast<float4*>(
            C + (size_t)row * N_DIM + jt * BN) + (threadIdx.x & 7);
        const float4 zv = make_float4(0.f, 0.f, 0.f, 0.f);
#pragma unroll
        for (int k = 0; k < 8; k++) dst[k * 8] = zv;
    }
}

// ---------------- Main GEMM (R11 config) ----------------

// Lower-triangle 128x256 tiles: jt in [0,14], it in [2jt+2, 31] -> 240 tiles,
// 960 slabs of 32 rows x 256 cols. Zeroed by GEMM CTAs (fire-and-forget).
#define N_LOWER_SLABS 960

__global__ __launch_bounds__(NTHREADS, 1)
void triu_gemm_f16mma_kernel(float* __restrict__ C)
{
    extern __shared__ __half smh[];
    const uint32_t smb = smem_u32(smh);

    const int tid  = threadIdx.x;
    const int wid  = tid >> 5;
    const int lane = tid & 31;
    const int qrow = lane >> 2;
    const int qcol = lane & 3;

    // ---- Zero this CTA's share of lower-triangle C (independent stores) ----
    for (int s = blockIdx.x; s < N_LOWER_SLABS; s += gridDim.x) {
        const int t = s >> 2;                    // lower-tile index [0, 240)
        const int sub = s & 3;
        int off = 0, jz = 0;
        for (; jz < 15; jz++) {                  // count 30 - 2*jz tiles per jt
            const int c = 30 - 2 * jz;
            if (t < off + c) break;
            off += c;
        }
        const int iz = 2 * jz + 2 + (t - off);
        const int row = iz * BM + sub * 32 + (tid >> 3);
        float4* dst = reinterpret_cast<float4*>(
            C + (size_t)row * N_DIM + jz * BN) + (tid & 7);
        const float4 zv = make_float4(0.f, 0.f, 0.f, 0.f);
#pragma unroll
        for (int k = 0; k < 8; k++) dst[k * 8] = zv;
    }

    // ---- Decode blockIdx -> (it, jt, k range) ----
    int it, jt, k_beg, k_end, L;
    {
        int r = blockIdx.x;
        L = 32;
        int jt0, p, njt;
        for (;; L--) {
            jt0 = (L - 1) >> 1;
            p = (L + 7) >> 3;
            njt = 16 - jt0;
            if (r < njt * p) break;
            r -= njt * p;
        }
        jt = jt0 + r / p;
        const int q = r % p;
        it = 2 * jt + 2 - L;
        k_beg = (it + (q * L) / p) * 128;
        k_end = (it + ((q + 1) * L) / p) * 128;
    }
    const int nch = (k_end - k_beg) / BK;
    const int split = (L > SPLIT_L);

    const int row0 = it * BM;
    const int col0 = jt * BN;

    const int wm = (wid & 1) * 64;
    const int wn = (wid >> 1) * 64;

    float acc[4][8][4];
#pragma unroll
    for (int i = 0; i < 4; i++)
#pragma unroll
        for (int j = 0; j < 8; j++)
#pragma unroll
            for (int r2 = 0; r2 < 4; r2++) acc[i][j][r2] = 0.0f;

    const int arow = tid >> 3;
    const int aseg = tid & 7;

    const __half* Ag = g_Ah + (size_t)(row0 + arow) * N_DIM + aseg * 8;
    const __half* Bg = g_Bt + (size_t)(col0 + arow) * N_DIM + aseg * 8;

#define LOAD_STAGE(s, kc)                                                        \
    do {                                                                         \
        const uint32_t abase = smb + ((s) * A_STAGE_H) * 2;                      \
        const uint32_t bbase = smb + (B_BASE_H + (s) * B_STAGE_H) * 2;           \
        _Pragma("unroll")                                                        \
        for (int r1 = 0; r1 < 4; r1++)                                          \
            cp_async16(abase + ((arow + r1 * 32) * APh + aseg * 8) * 2,          \
                       Ag + (size_t)(r1 * 32) * N_DIM + (kc));                   \
        _Pragma("unroll")                                                        \
        for (int r1 = 0; r1 < 8; r1++)                                          \
            cp_async16(bbase + ((arow + r1 * 32) * BPh + aseg * 8) * 2,          \
                       Bg + (size_t)(r1 * 32) * N_DIM + (kc));                   \
    } while (0)

    const uint32_t a_lane =
        ((wm + ((lane >> 3) & 1) * 8 + (lane & 7)) * APh + (lane >> 4) * 8) * 2;
    const uint32_t b_lane =
        ((wn + (lane >> 4) * 8 + (lane & 7)) * BPh + ((lane >> 3) & 1) * 8) * 2;

#pragma unroll
    for (int s = 0; s < STAGES - 1; s++) {
        if (s < nch) LOAD_STAGE(s, k_beg + s * BK);
        asm volatile("cp.async.commit_group;" ::: "memory");
    }

    for (int i = 0; i < nch; i++) {
        asm volatile("cp.async.wait_group %0;" :: "n"(STAGES - 2) : "memory");
        __syncthreads();

        if (i + STAGES - 1 < nch)
            LOAD_STAGE((i + STAGES - 1) % STAGES, k_beg + (i + STAGES - 1) * BK);
        asm volatile("cp.async.commit_group;" ::: "memory");

        const int s = i % STAGES;
        const uint32_t a_base = smb + (s * A_STAGE_H) * 2 + a_lane;
        const uint32_t b_base = smb + (B_BASE_H + s * B_STAGE_H) * 2 + b_lane;

        uint32_t af[2][4][4], bf[2][8][2];
#pragma unroll
        for (int mt = 0; mt < 4; mt++)
            LDSM_X4(af[0][mt][0], af[0][mt][1], af[0][mt][2], af[0][mt][3],
                    a_base + (mt * 16 * APh) * 2);
#pragma unroll
        for (int p = 0; p < 4; p++)
            LDSM_X4(bf[0][2 * p][0], bf[0][2 * p][1],
                    bf[0][2 * p + 1][0], bf[0][2 * p + 1][1],
                    b_base + (p * 16 * BPh) * 2);

#pragma unroll
        for (int ks = 0; ks < BK / 16; ks++) {
            const int cur = ks & 1;
            const int nxt = cur ^ 1;
            if (ks < BK / 16 - 1) {
                const uint32_t ko = ((ks + 1) * 16) * 2;
#pragma unroll
                for (int mt = 0; mt < 4; mt++)
                    LDSM_X4(af[nxt][mt][0], af[nxt][mt][1],
                            af[nxt][mt][2], af[nxt][mt][3],
                            a_base + (mt * 16 * APh) * 2 + ko);
#pragma unroll
                for (int p = 0; p < 4; p++)
                    LDSM_X4(bf[nxt][2 * p][0], bf[nxt][2 * p][1],
                            bf[nxt][2 * p + 1][0], bf[nxt][2 * p + 1][1],
                            b_base + (p * 16 * BPh) * 2 + ko);
            }
#pragma unroll
            for (int mt = 0; mt < 4; mt++)
#pragma unroll
                for (int nt = 0; nt < 8; nt++) {
                    asm volatile(
                        "mma.sync.aligned.m16n8k16.row.col.f32.f16.f16.f32 "
                        "{%0,%1,%2,%3}, {%4,%5,%6,%7}, {%8,%9}, {%0,%1,%2,%3};"
                        : "+f"(acc[mt][nt][0]), "+f"(acc[mt][nt][1]),
                          "+f"(acc[mt][nt][2]), "+f"(acc[mt][nt][3])
                        : "r"(af[cur][mt][0]), "r"(af[cur][mt][1]),
                          "r"(af[cur][mt][2]), "r"(af[cur][mt][3]),
                          "r"(bf[cur][nt][0]), "r"(bf[cur][nt][1]));
                }
        }
    }
    __syncthreads();

    // ---- Epilogue ----
    if (split) {
#pragma unroll
        for (int mt = 0; mt < 4; mt++) {
            const int r_lo = row0 + wm + mt * 16 + qrow;
            float* crow_lo = C + (size_t)r_lo * N_DIM;
            float* crow_hi = crow_lo + (size_t)8 * N_DIM;
#pragma unroll
            for (int nt = 0; nt < 8; nt++) {
                const int gc = col0 + wn + nt * 8 + qcol * 2;
                red_add_f32(crow_lo + gc,     acc[mt][nt][0]);
                red_add_f32(crow_lo + gc + 1, acc[mt][nt][1]);
                red_add_f32(crow_hi + gc,     acc[mt][nt][2]);
                red_add_f32(crow_hi + gc + 1, acc[mt][nt][3]);
            }
        }
    } else {
#pragma unroll
        for (int mt = 0; mt < 4; mt++) {
            const int r_lo = row0 + wm + mt * 16 + qrow;
            const int r_hi = r_lo + 8;
            float* crow_lo = C + (size_t)r_lo * N_DIM;
            float* crow_hi = C + (size_t)r_hi * N_DIM;
#pragma unroll
            for (int nt = 0; nt < 8; nt++) {
                const int gc = col0 + wn + nt * 8 + qcol * 2;
                float2 v0, v1;
                v0.x = (gc + 0 >= r_lo) ? acc[mt][nt][0] : 0.0f;
                v0.y = (gc + 1 >= r_lo) ? acc[mt][nt][1] : 0.0f;
                v1.x = (gc + 0 >= r_hi) ? acc[mt][nt][2] : 0.0f;
                v1.y = (gc + 1 >= r_hi) ? acc[mt][nt][3] : 0.0f;
                *reinterpret_cast<float2*>(crow_lo + gc) = v0;
                *reinterpret_cast<float2*>(crow_hi + gc) = v1;
            }
        }
    }
}

extern "C" void kernel_launch(void* const* d_in, const int* in_sizes, int n_in,
                              void* d_out, int out_size) {
    const float* A = (const float*)d_in[0];
    const float* B = (const float*)d_in[1];
    float* C = (float*)d_out;

    int cnt = 0;
    for (int L = 32; L >= 1; L--) {
        const int jt0 = (L - 1) >> 1;
        const int p = (L + 7) >> 3;
        cnt += (16 - jt0) * p;
    }

    cudaFuncSetAttribute(triu_gemm_f16mma_kernel,
                         cudaFuncAttributeMaxDynamicSharedMemorySize, SMEM_H * 2);

    prep_kernel<<<PREP_A + PREP_B + PREP_Z, 256>>>(A, B, C);
    triu_gemm_f16mma_kernel<<<cnt, NTHREADS, SMEM_H * 2>>>(C);
}